// round 15
// baseline (speedup 1.0000x reference)
#include <cuda_runtime.h>
#include <cuda_fp16.h>
#include <cstdint>

#define NN      4096
#define FIN     256
#define FOUT    64
#define HEADS   4
#define NF      (NN * FOUT)
#define ITILE   128
#define JCHUNK  64
#define NSPLIT  2
#define NCHUNK  (NN / NSPLIT / JCHUNK)   // 32 chunks per block
#define NCH_ROW (NN / 32)                // 128 mask words per adj row
#define HT_B    (FOUT * JCHUNK * 2)      // 8192 bytes per Ht buffer
#define GROWS   8                        // rows per gemm_h block

// ---------------- device scratch ----------------
__device__ float4 g_i4[NN * HEADS];            // {ei, exp(ei), exp(.2ei), 0}
__device__ uint2  g_jh2[HEADS * (NN / 2)];     // per (head, node-pair): {E2, N2} half2s
__device__ __half g_hT[HEADS * FOUT * NN];     // transposed h, fp16
__device__ uint2  g_adjb2[NN * (NCH_ROW / 2)]; // 64-bit mask per (row, 64-col chunk)
__device__ float  g_partC[NSPLIT * HEADS * NN * FOUT];
__device__ float  g_partZ[NSPLIT * HEADS * NN];

// ---------------- PTX helpers ----------------
__device__ __forceinline__ uint32_t smem_u32(const void* p) {
    uint32_t a;
    asm("{ .reg .u64 t; cvta.to.shared.u64 t, %1; cvt.u32.u64 %0, t; }" : "=r"(a) : "l"(p));
    return a;
}
__device__ __forceinline__ void ldsm4(uint32_t* r, uint32_t addr) {
    asm volatile("ldmatrix.sync.aligned.m8n8.x4.shared.b16 {%0,%1,%2,%3}, [%4];"
                 : "=r"(r[0]), "=r"(r[1]), "=r"(r[2]), "=r"(r[3]) : "r"(addr));
}
__device__ __forceinline__ void ldsm2(uint32_t& r0, uint32_t& r1, uint32_t addr) {
    asm volatile("ldmatrix.sync.aligned.m8n8.x2.shared.b16 {%0,%1}, [%2];"
                 : "=r"(r0), "=r"(r1) : "r"(addr));
}
__device__ __forceinline__ void mma16816(float* c, const uint32_t* a,
                                         uint32_t b0, uint32_t b1) {
    asm volatile("mma.sync.aligned.m16n8k16.row.col.f32.f16.f16.f32 "
                 "{%0,%1,%2,%3}, {%4,%5,%6,%7}, {%8,%9}, {%0,%1,%2,%3};"
                 : "+f"(c[0]), "+f"(c[1]), "+f"(c[2]), "+f"(c[3])
                 : "r"(a[0]), "r"(a[1]), "r"(a[2]), "r"(a[3]), "r"(b0), "r"(b1));
}
#define CP_ASYNC16(dst, src) \
    asm volatile("cp.async.cg.shared.global [%0], [%1], 16;" :: "r"(dst), "l"(src) : "memory")
#define CP_ASYNC8(dst, src) \
    asm volatile("cp.async.ca.shared.global [%0], [%1], 8;"  :: "r"(dst), "l"(src) : "memory")
#define CP_COMMIT() asm volatile("cp.async.commit_group;" ::: "memory")
#define CP_WAIT1()  asm volatile("cp.async.wait_group 1;"  ::: "memory")
// XOR swizzle: permute 16B chunks within a 128B row by row&7 (conflict-free LDSM)
__device__ __forceinline__ uint32_t swz(int row, int byteInRow) {
    return (uint32_t)(row * 128 + ((((byteInRow >> 4) ^ (row & 7)) << 4) | (byteInRow & 15)));
}
// w2 = max(Ei*Ej, Ni*Nj) in half2, then AND with 2-bit-derived lane mask
__device__ __forceinline__ uint32_t wgen(__half2 hE, __half2 hN,
                                         uint32_t Ep, uint32_t Np, unsigned b2) {
    const __half2 Eh = *reinterpret_cast<const __half2*>(&Ep);
    const __half2 Nh = *reinterpret_cast<const __half2*>(&Np);
    const __half2 w2 = __hmax2(__hmul2(hE, Eh), __hmul2(hN, Nh));
    const uint32_t m = ((b2 & 1u) * 0xFFFFu) | (((b2 >> 1) & 1u) * 0xFFFF0000u);
    return (*reinterpret_cast<const uint32_t*>(&w2)) & m;
}

// ---------------- kernel 1: x@W (reg-pipelined W LDG) + hT + e-scores + pack -------
__global__ void __launch_bounds__(256) gemm_h_kernel(const float* __restrict__ x,
                                                     const float* __restrict__ W,
                                                     const float* __restrict__ a,
                                                     const int* __restrict__ adj) {
    __shared__ __align__(16) float xs[GROWS * FIN];   // 8 KB; [r][k]; reused for escore
    __shared__ float as[128];
    const int n0 = blockIdx.x * GROWS;
    const int t  = threadIdx.x;
    const int lane = t & 31;
    const int ww   = t >> 5;

    if (t < 128) as[t] = a[t];
    // load x tile ([8][256] floats, linear float4 copy)
    {
        const float4* src = (const float4*)(x + (size_t)n0 * FIN);
        float4* dst = (float4*)xs;
        dst[t]       = src[t];
        dst[t + 256] = src[t + 256];
    }
    __syncthreads();

    float acc[GROWS];
    #pragma unroll
    for (int r = 0; r < GROWS; ++r) acc[r] = 0.0f;

    // register double-buffered W loads: prefetch k+4 while FMAing k
    float wc[4];
    #pragma unroll
    for (int kk = 0; kk < 4; ++kk) wc[kk] = W[kk * 256 + t];

    for (int k = 0; k < FIN; k += 4) {
        float wn[4] = {0.0f, 0.0f, 0.0f, 0.0f};
        if (k + 4 < FIN) {
            #pragma unroll
            for (int kk = 0; kk < 4; ++kk) wn[kk] = W[(k + 4 + kk) * 256 + t];
        }
        #pragma unroll
        for (int r = 0; r < GROWS; ++r) {
            const float4 xv = *(const float4*)&xs[r * FIN + k];
            acc[r] = fmaf(xv.x, wc[0], acc[r]);
            acc[r] = fmaf(xv.y, wc[1], acc[r]);
            acc[r] = fmaf(xv.z, wc[2], acc[r]);
            acc[r] = fmaf(xv.w, wc[3], acc[r]);
        }
        #pragma unroll
        for (int kk = 0; kk < 4; ++kk) wc[kk] = wn[kk];
    }

    // thread t holds column t (= head*64+f) for rows n0..n0+7 -> direct hT write
    {
        unsigned hp[GROWS / 2];
        #pragma unroll
        for (int r = 0; r < GROWS; r += 2) {
            const __half h0 = __float2half_rn(acc[r]);
            const __half h1 = __float2half_rn(acc[r + 1]);
            hp[r >> 1] = ((unsigned)__half_as_ushort(h1) << 16) | __half_as_ushort(h0);
        }
        *(uint4*)&g_hT[(size_t)t * NN + n0] = make_uint4(hp[0], hp[1], hp[2], hp[3]);
    }

    // ---- fused escore: stage h-tile in smem, 64-wide dots ----
    __syncthreads();
    #pragma unroll
    for (int r = 0; r < GROWS; ++r) xs[r * FIN + t] = acc[r];
    __syncthreads();

    if (t < 64) {
        const int r     = t >> 3;        // 0..7
        const int g     = t & 7;
        const int hd    = g >> 1;
        const int which = g & 1;
        const float* av = as + which * 64;
        const float* hr = &xs[r * FIN + hd * 64];
        float s = 0.0f;
        #pragma unroll
        for (int f = 0; f < 64; ++f) s = fmaf(hr[f], av[f], s);
        const int n = n0 + r;
        const float E = __expf(s);
        const float N = __expf(0.2f * s);
        if (which == 0) {
            g_i4[n * HEADS + hd] = make_float4(s, E, N, 0.0f);
        } else {
            __half* jb = (__half*)&g_jh2[(size_t)hd * (NN / 2) + (n >> 1)];
            jb[n & 1]       = __float2half_rn(E);
            jb[2 + (n & 1)] = __float2half_rn(N);
        }
    }

    // ---- fused adj pack (arithmetic, int4-vectorized, NO ballots) ----
    // warp ww packs row n0+ww; lane owns words {lane, lane+32, lane+64, lane+96};
    // word wi: bit b <-> col 32*wi + b.
    {
        const int row = n0 + ww;
        const int4* src = (const int4*)(adj + (size_t)row * NN);
        unsigned* dst = (unsigned*)&g_adjb2[(size_t)row * (NCH_ROW / 2)];
        #pragma unroll 1
        for (int m = 0; m < 4; ++m) {
            const int wi = m * 32 + lane;
            int4 v[8];
            #pragma unroll
            for (int q = 0; q < 8; ++q) v[q] = src[wi * 8 + q];   // 8 LDG.128 in flight
            unsigned word = 0;
            #pragma unroll
            for (int q = 0; q < 8; ++q) {
                const unsigned nib = (v[q].x != 0 ? 1u : 0u) | (v[q].y != 0 ? 2u : 0u)
                                   | (v[q].z != 0 ? 4u : 0u) | (v[q].w != 0 ? 8u : 0u);
                word |= nib << (4 * q);
            }
            dst[wi] = word;
        }
    }
}

// ---------------- kernel 2: register-gen mma attention (half2 max-trick, Z via MMA) --
__global__ void __launch_bounds__(256, 2) gat_mma_kernel() {
    __shared__ __align__(128) __half  Ht[3][FOUT * JCHUNK];   // 3 x 8 KB [f][j] swizzled
    __shared__ __align__(16)  uint2   jsm[3][JCHUNK / 2];     // 3 x 256 B {E2,N2} per pair
    __shared__ __align__(32)  __half  OnesT[8][16];           // B-tile: row0(n=0) = ones

    const int t     = threadIdx.x;
    const int lane  = t & 31;
    const int w     = t >> 5;
    const int tid   = lane & 3;
    const int gr    = lane >> 2;
    const int head  = blockIdx.y;
    const int i0    = blockIdx.x * ITILE;
    const int split = blockIdx.z;
    const int jbase = split * (NN / NSPLIT);
    const int cg0   = split * NCHUNK;

    const uint32_t htb = smem_u32(Ht);
    const uint32_t onb = smem_u32(OnesT);

    if (t < 128) ((__half*)OnesT)[t] = (t < 16) ? __float2half(1.0f) : __float2half(0.0f);

    // per-thread row pair (A-fragment layout): rows rA, rA+8
    const int rA = w * 16 + gr;
    const float4 e0 = g_i4[(i0 + rA) * HEADS + head];
    const float4 e1 = g_i4[(i0 + rA + 8) * HEADS + head];
    const __half2 hE0 = __float2half2_rn(e0.y), hN0 = __float2half2_rn(e0.z);
    const __half2 hE1 = __float2half2_rn(e1.y), hN1 = __float2half2_rn(e1.z);

    // Ht staging coords
    const int hrow = t >> 2;
    const int s0   = (t & 3) * 2;
    const __half* hsrc = &g_hT[(size_t)(head * FOUT + hrow) * NN + jbase];
    const uint2* jsrc = &g_jh2[(size_t)head * (NN / 2) + jbase / 2];

    // adj masks, double-buffered in regs
    const uint2* adjr0 = &g_adjb2[(size_t)(i0 + rA) * (NCH_ROW / 2) + cg0];
    const uint2* adjr1 = &g_adjb2[(size_t)(i0 + rA + 8) * (NCH_ROW / 2) + cg0];
    uint2 awc0 = adjr0[0], awc1 = adjr1[0];
    uint2 awn0, awn1;

    float acc[8][4];
    #pragma unroll
    for (int n = 0; n < 8; ++n)
        #pragma unroll
        for (int k = 0; k < 4; ++k) acc[n][k] = 0.0f;
    float accZ[4] = {0.0f, 0.0f, 0.0f, 0.0f};

    // ---- prologue: stage chunks 0,1 ----
    #pragma unroll
    for (int pc = 0; pc < 2; ++pc) {
        const uint32_t hb = htb + pc * HT_B;
        CP_ASYNC16(hb + swz(hrow, s0 * 16),       hsrc + pc * JCHUNK + s0 * 8);
        CP_ASYNC16(hb + swz(hrow, (s0 + 1) * 16), hsrc + pc * JCHUNK + (s0 + 1) * 8);
        if (t < JCHUNK / 2)
            CP_ASYNC8(smem_u32(&jsm[pc][t]), jsrc + pc * (JCHUNK / 2) + t);
        CP_COMMIT();
    }

    __syncthreads();   // OnesT visible
    uint32_t oz0, oz1;
    ldsm2(oz0, oz1, onb + (lane & 7) * 32 + ((lane >> 3) & 1) * 16);

    for (int c = 0; c < NCHUNK; ++c) {
        const int b = c % 3;
        CP_WAIT1();
        __syncthreads();

        // ---- issue chunk c+2 into buffer (c+2)%3 ----
        if (c + 2 < NCHUNK) {
            const int b2 = (c + 2) % 3;
            const uint32_t hb = htb + b2 * HT_B;
            CP_ASYNC16(hb + swz(hrow, s0 * 16),       hsrc + (c + 2) * JCHUNK + s0 * 8);
            CP_ASYNC16(hb + swz(hrow, (s0 + 1) * 16), hsrc + (c + 2) * JCHUNK + (s0 + 1) * 8);
            if (t < JCHUNK / 2)
                CP_ASYNC8(smem_u32(&jsm[b2][t]), jsrc + (c + 2) * (JCHUNK / 2) + t);
        }
        CP_COMMIT();

        if (c + 1 < NCHUNK) { awn0 = adjr0[c + 1]; awn1 = adjr1[c + 1]; }

        const uint32_t hb = htb + b * HT_B;
        const uint2* jrow = jsm[b];

        #pragma unroll
        for (int ks = 0; ks < 4; ++ks) {
            // B fragments: 4 n-tiles of 16 f-cols
            uint32_t bf[4][4];
            {
                const int grp  = lane >> 3;
                const int bkcB = (ks * 2 + (grp & 1)) * 16;
                const int rofs = (grp >> 1) * 8 + (lane & 7);
                #pragma unroll
                for (int np = 0; np < 4; ++np)
                    ldsm4(bf[np], hb + swz(np * 16 + rofs, bkcB));
            }
            // j factors: pair A = cols {ks*16+2tid, +1}, pair B = +8
            const uint2 jA = jrow[ks * 8 + tid];
            const uint2 jB = jrow[ks * 8 + tid + 4];
            // adj bits
            const unsigned m0 = (ks < 2) ? awc0.x : awc0.y;
            const unsigned m1 = (ks < 2) ? awc1.x : awc1.y;
            const int base = (ks & 1) * 16 + 2 * tid;
            const unsigned r0b = m0 >> base;
            const unsigned r1b = m1 >> base;
            // generate A fragment: w = max(Ei*Ej, Ni*Nj) & adjmask  (half2, 2 cols/op)
            uint32_t af[4];
            af[0] = wgen(hE0, hN0, jA.x, jA.y, r0b & 3u);
            af[1] = wgen(hE1, hN1, jA.x, jA.y, r1b & 3u);
            af[2] = wgen(hE0, hN0, jB.x, jB.y, (r0b >> 8) & 3u);
            af[3] = wgen(hE1, hN1, jB.x, jB.y, (r1b >> 8) & 3u);
            // 8 HMMA + 1 Z-HMMA (ones column)
            #pragma unroll
            for (int np = 0; np < 4; ++np) {
                mma16816(acc[np * 2],     af, bf[np][0], bf[np][1]);
                mma16816(acc[np * 2 + 1], af, bf[np][2], bf[np][3]);
            }
            mma16816(accZ, af, oz0, oz1);
        }
        awc0 = awn0;
        awc1 = awn1;
    }

    // ---- Z: col 0 of the Z-tile (held by tid==0 lanes) ----
    if (tid == 0) {
        float* zb = g_partZ + (size_t)(split * HEADS + head) * NN + i0;
        zb[rA]     = accZ[0];
        zb[rA + 8] = accZ[2];
    }

    // ---- epilogue: store unnormalized partial C ----
    {
        float* cbase = g_partC + (size_t)(split * HEADS + head) * NN * FOUT;
        float* p0 = cbase + (size_t)(i0 + rA) * FOUT + 2 * tid;
        float* p1 = cbase + (size_t)(i0 + rA + 8) * FOUT + 2 * tid;
        #pragma unroll
        for (int np = 0; np < 4; ++np) {
            #pragma unroll
            for (int p = 0; p < 2; ++p) {
                const int nt = np * 2 + p;
                const int cb = np * 16 + p * 8;
                *(float2*)(p0 + cb) = make_float2(acc[nt][0], acc[nt][1]);
                *(float2*)(p1 + cb) = make_float2(acc[nt][2], acc[nt][3]);
            }
        }
    }
}

// ---------------- kernel 3: combine splits, normalize, mean heads ----------
__global__ void __launch_bounds__(256) combine_kernel(float* __restrict__ out) {
    const int idx = blockIdx.x * 256 + threadIdx.x;   // i*64 + f
    const int i = idx >> 6;
    float r = 0.0f;
    #pragma unroll
    for (int h = 0; h < HEADS; ++h) {
        float cs = 0.0f, zs = 0.0f;
        #pragma unroll
        for (int s = 0; s < NSPLIT; ++s) {
            cs += g_partC[(size_t)(s * HEADS + h) * NN * FOUT + idx];
            zs += g_partZ[(size_t)(s * HEADS + h) * NN + i];
        }
        r += cs / zs;
    }
    out[idx] = 0.25f * r;
}

// ---------------- launcher ----------------
extern "C" void kernel_launch(void* const* d_in, const int* in_sizes, int n_in,
                              void* d_out, int out_size) {
    const float* x = nullptr;
    const int*   adj = nullptr;
    const float* W = nullptr;
    const float* a = nullptr;
    for (int i = 0; i < n_in; ++i) {
        switch (in_sizes[i]) {
            case 1048576:  x   = (const float*)d_in[i]; break;
            case 16777216: adj = (const int*)  d_in[i]; break;
            case 65536:    W   = (const float*)d_in[i]; break;
            case 128:      a   = (const float*)d_in[i]; break;
        }
    }
    float* out = (float*)d_out;

    gemm_h_kernel<<<NN / GROWS, 256>>>(x, W, a, adj);
    gat_mma_kernel<<<dim3(NN / ITILE, HEADS, NSPLIT), 256>>>();
    combine_kernel<<<NF / 256, 256>>>(out);
}

// round 16
// speedup vs baseline: 1.1488x; 1.1488x over previous
#include <cuda_runtime.h>
#include <cuda_fp16.h>
#include <cstdint>

#define NN      4096
#define FIN     256
#define FOUT    64
#define HEADS   4
#define NF      (NN * FOUT)
#define ITILE   128
#define JCHUNK  64
#define NSPLIT  2
#define NCHUNK  (NN / NSPLIT / JCHUNK)   // 32 chunks per block
#define NGRP    (NN / 128)               // 32 mask groups (uint4) per adj row
#define HT_B    (FOUT * JCHUNK * 2)      // 8192 bytes per Ht buffer
#define GROWS   8                        // rows per gemm_h block

// ---------------- device scratch ----------------
__device__ float4 g_i4[NN * HEADS];            // {ei, exp(ei), exp(.2ei), 0}
__device__ uint2  g_jh2[HEADS * (NN / 2)];     // per (head, node-pair): {E2, N2} half2s
__device__ __half g_hT[HEADS * FOUT * NN];     // transposed h, fp16
__device__ uint4  g_adjb4[NN * NGRP];          // per (row, 128-col group): 4 ballot words;
                                               //   word k bit l <-> col 128g + 4l + k
__device__ float  g_partC[NSPLIT * HEADS * NN * FOUT];
__device__ float  g_partZ[NSPLIT * HEADS * NN];

// ---------------- PTX helpers ----------------
__device__ __forceinline__ uint32_t smem_u32(const void* p) {
    uint32_t a;
    asm("{ .reg .u64 t; cvta.to.shared.u64 t, %1; cvt.u32.u64 %0, t; }" : "=r"(a) : "l"(p));
    return a;
}
__device__ __forceinline__ void ldsm4(uint32_t* r, uint32_t addr) {
    asm volatile("ldmatrix.sync.aligned.m8n8.x4.shared.b16 {%0,%1,%2,%3}, [%4];"
                 : "=r"(r[0]), "=r"(r[1]), "=r"(r[2]), "=r"(r[3]) : "r"(addr));
}
__device__ __forceinline__ void ldsm2(uint32_t& r0, uint32_t& r1, uint32_t addr) {
    asm volatile("ldmatrix.sync.aligned.m8n8.x2.shared.b16 {%0,%1}, [%2];"
                 : "=r"(r0), "=r"(r1) : "r"(addr));
}
__device__ __forceinline__ void mma16816(float* c, const uint32_t* a,
                                         uint32_t b0, uint32_t b1) {
    asm volatile("mma.sync.aligned.m16n8k16.row.col.f32.f16.f16.f32 "
                 "{%0,%1,%2,%3}, {%4,%5,%6,%7}, {%8,%9}, {%0,%1,%2,%3};"
                 : "+f"(c[0]), "+f"(c[1]), "+f"(c[2]), "+f"(c[3])
                 : "r"(a[0]), "r"(a[1]), "r"(a[2]), "r"(a[3]), "r"(b0), "r"(b1));
}
#define CP_ASYNC16(dst, src) \
    asm volatile("cp.async.cg.shared.global [%0], [%1], 16;" :: "r"(dst), "l"(src) : "memory")
#define CP_ASYNC8(dst, src) \
    asm volatile("cp.async.ca.shared.global [%0], [%1], 8;"  :: "r"(dst), "l"(src) : "memory")
#define CP_COMMIT() asm volatile("cp.async.commit_group;" ::: "memory")
#define CP_WAIT1()  asm volatile("cp.async.wait_group 1;"  ::: "memory")
// XOR swizzle: permute 16B chunks within a 128B row by row&7 (conflict-free LDSM)
__device__ __forceinline__ uint32_t swz(int row, int byteInRow) {
    return (uint32_t)(row * 128 + ((((byteInRow >> 4) ^ (row & 7)) << 4) | (byteInRow & 15)));
}
// w2 = max(Ei*Ej, Ni*Nj) in half2, then AND with 2-bit-derived lane mask
__device__ __forceinline__ uint32_t wgen(__half2 hE, __half2 hN,
                                         uint32_t Ep, uint32_t Np, unsigned b2) {
    const __half2 Eh = *reinterpret_cast<const __half2*>(&Ep);
    const __half2 Nh = *reinterpret_cast<const __half2*>(&Np);
    const __half2 w2 = __hmax2(__hmul2(hE, Eh), __hmul2(hN, Nh));
    const uint32_t m = ((b2 & 1u) * 0xFFFFu) | (((b2 >> 1) & 1u) * 0xFFFF0000u);
    return (*reinterpret_cast<const uint32_t*>(&w2)) & m;
}

// ---------------- kernel 1: x@W + hT + e-scores + COALESCED ballot pack ----------
__global__ void __launch_bounds__(256) gemm_h_kernel(const float* __restrict__ x,
                                                     const float* __restrict__ W,
                                                     const float* __restrict__ a,
                                                     const int* __restrict__ adj) {
    __shared__ __align__(16) float xs[GROWS * FIN];   // 8 KB; [r][k]; reused for escore
    __shared__ float as[128];
    const int n0 = blockIdx.x * GROWS;
    const int t  = threadIdx.x;
    const int lane = t & 31;
    const int ww   = t >> 5;

    if (t < 128) as[t] = a[t];
    // load x tile ([8][256] floats, linear float4 copy)
    {
        const float4* src = (const float4*)(x + (size_t)n0 * FIN);
        float4* dst = (float4*)xs;
        dst[t]       = src[t];
        dst[t + 256] = src[t + 256];
    }
    __syncthreads();

    float acc[GROWS];
    #pragma unroll
    for (int r = 0; r < GROWS; ++r) acc[r] = 0.0f;

    // register double-buffered W loads: prefetch k+4 while FMAing k
    float wc[4];
    #pragma unroll
    for (int kk = 0; kk < 4; ++kk) wc[kk] = W[kk * 256 + t];

    for (int k = 0; k < FIN; k += 4) {
        float wn[4] = {0.0f, 0.0f, 0.0f, 0.0f};
        if (k + 4 < FIN) {
            #pragma unroll
            for (int kk = 0; kk < 4; ++kk) wn[kk] = W[(k + 4 + kk) * 256 + t];
        }
        #pragma unroll
        for (int r = 0; r < GROWS; ++r) {
            const float4 xv = *(const float4*)&xs[r * FIN + k];
            acc[r] = fmaf(xv.x, wc[0], acc[r]);
            acc[r] = fmaf(xv.y, wc[1], acc[r]);
            acc[r] = fmaf(xv.z, wc[2], acc[r]);
            acc[r] = fmaf(xv.w, wc[3], acc[r]);
        }
        #pragma unroll
        for (int kk = 0; kk < 4; ++kk) wc[kk] = wn[kk];
    }

    // thread t holds column t (= head*64+f) for rows n0..n0+7 -> direct hT write
    {
        unsigned hp[GROWS / 2];
        #pragma unroll
        for (int r = 0; r < GROWS; r += 2) {
            const __half h0 = __float2half_rn(acc[r]);
            const __half h1 = __float2half_rn(acc[r + 1]);
            hp[r >> 1] = ((unsigned)__half_as_ushort(h1) << 16) | __half_as_ushort(h0);
        }
        *(uint4*)&g_hT[(size_t)t * NN + n0] = make_uint4(hp[0], hp[1], hp[2], hp[3]);
    }

    // ---- fused escore: stage h-tile in smem, 64-wide dots ----
    __syncthreads();
    #pragma unroll
    for (int r = 0; r < GROWS; ++r) xs[r * FIN + t] = acc[r];
    __syncthreads();

    if (t < 64) {
        const int r     = t >> 3;        // 0..7
        const int g     = t & 7;
        const int hd    = g >> 1;
        const int which = g & 1;
        const float* av = as + which * 64;
        const float* hr = &xs[r * FIN + hd * 64];
        float s = 0.0f;
        #pragma unroll
        for (int f = 0; f < 64; ++f) s = fmaf(hr[f], av[f], s);
        const int n = n0 + r;
        const float E = __expf(s);
        const float N = __expf(0.2f * s);
        if (which == 0) {
            g_i4[n * HEADS + hd] = make_float4(s, E, N, 0.0f);
        } else {
            __half* jb = (__half*)&g_jh2[(size_t)hd * (NN / 2) + (n >> 1)];
            jb[n & 1]       = __float2half_rn(E);
            jb[2 + (n & 1)] = __float2half_rn(N);
        }
    }

    // ---- fused adj pack: COALESCED int4 loads + 4 ballots per 128-col group ----
    // warp ww packs row n0+ww. Group g: lane loads int4 #(g*32+lane) (contiguous
    // 512B). ballot b_k bit l <-> col 128g + 4l + k. lane 0 stores uint4 per group.
    {
        const int row = n0 + ww;
        const int4* src = (const int4*)(adj + (size_t)row * NN);
        uint4* dst = &g_adjb4[(size_t)row * NGRP];
        for (int m = 0; m < NGRP; m += 8) {
            int4 v[8];
            #pragma unroll
            for (int q = 0; q < 8; ++q)
                v[q] = src[(m + q) * 32 + lane];     // 8 coalesced LDG.128 in flight
            uint4 bw[8];
            #pragma unroll
            for (int q = 0; q < 8; ++q) {
                bw[q].x = __ballot_sync(0xffffffffu, v[q].x != 0);
                bw[q].y = __ballot_sync(0xffffffffu, v[q].y != 0);
                bw[q].z = __ballot_sync(0xffffffffu, v[q].z != 0);
                bw[q].w = __ballot_sync(0xffffffffu, v[q].w != 0);
            }
            if (lane == 0) {
                #pragma unroll
                for (int q = 0; q < 8; ++q) dst[m + q] = bw[q];
            }
        }
    }
}

// ---------------- kernel 2: register-gen mma attention (half2 max-trick, Z via MMA) --
__global__ void __launch_bounds__(256, 2) gat_mma_kernel() {
    __shared__ __align__(128) __half  Ht[3][FOUT * JCHUNK];   // 3 x 8 KB [f][j] swizzled
    __shared__ __align__(16)  uint2   jsm[3][JCHUNK / 2];     // 3 x 256 B {E2,N2} per pair
    __shared__ __align__(32)  __half  OnesT[8][16];           // B-tile: row0(n=0) = ones

    const int t     = threadIdx.x;
    const int lane  = t & 31;
    const int w     = t >> 5;
    const int tid   = lane & 3;
    const int gr    = lane >> 2;
    const int head  = blockIdx.y;
    const int i0    = blockIdx.x * ITILE;
    const int split = blockIdx.z;
    const int jbase = split * (NN / NSPLIT);

    const uint32_t htb = smem_u32(Ht);
    const uint32_t onb = smem_u32(OnesT);

    if (t < 128) ((__half*)OnesT)[t] = (t < 16) ? __float2half(1.0f) : __float2half(0.0f);

    // per-thread row pair (A-fragment layout): rows rA, rA+8
    const int rA = w * 16 + gr;
    const float4 e0 = g_i4[(i0 + rA) * HEADS + head];
    const float4 e1 = g_i4[(i0 + rA + 8) * HEADS + head];
    const __half2 hE0 = __float2half2_rn(e0.y), hN0 = __float2half2_rn(e0.z);
    const __half2 hE1 = __float2half2_rn(e1.y), hN1 = __float2half2_rn(e1.z);

    // Ht staging coords
    const int hrow = t >> 2;
    const int s0   = (t & 3) * 2;
    const __half* hsrc = &g_hT[(size_t)(head * FOUT + hrow) * NN + jbase];
    const uint2* jsrc = &g_jh2[(size_t)head * (NN / 2) + jbase / 2];

    // adj mask groups (uint4 per 128 cols = 2 chunks), prefetched per chunk-pair
    const uint4* adjp0 = &g_adjb4[(size_t)(i0 + rA) * NGRP + split * (NCHUNK / 2)];
    const uint4* adjp1 = &g_adjb4[(size_t)(i0 + rA + 8) * NGRP + split * (NCHUNK / 2)];
    uint4 awc0 = adjp0[0], awc1 = adjp1[0];
    uint4 awn0, awn1;

    float acc[8][4];
    #pragma unroll
    for (int n = 0; n < 8; ++n)
        #pragma unroll
        for (int k = 0; k < 4; ++k) acc[n][k] = 0.0f;
    float accZ[4] = {0.0f, 0.0f, 0.0f, 0.0f};

    // ---- prologue: stage chunks 0,1 ----
    #pragma unroll
    for (int pc = 0; pc < 2; ++pc) {
        const uint32_t hb = htb + pc * HT_B;
        CP_ASYNC16(hb + swz(hrow, s0 * 16),       hsrc + pc * JCHUNK + s0 * 8);
        CP_ASYNC16(hb + swz(hrow, (s0 + 1) * 16), hsrc + pc * JCHUNK + (s0 + 1) * 8);
        if (t < JCHUNK / 2)
            CP_ASYNC8(smem_u32(&jsm[pc][t]), jsrc + pc * (JCHUNK / 2) + t);
        CP_COMMIT();
    }

    __syncthreads();   // OnesT visible
    uint32_t oz0, oz1;
    ldsm2(oz0, oz1, onb + (lane & 7) * 32 + ((lane >> 3) & 1) * 16);

    for (int c = 0; c < NCHUNK; ++c) {
        const int b = c % 3;
        CP_WAIT1();
        __syncthreads();

        // ---- issue chunk c+2 into buffer (c+2)%3 ----
        if (c + 2 < NCHUNK) {
            const int b2 = (c + 2) % 3;
            const uint32_t hb = htb + b2 * HT_B;
            CP_ASYNC16(hb + swz(hrow, s0 * 16),       hsrc + (c + 2) * JCHUNK + s0 * 8);
            CP_ASYNC16(hb + swz(hrow, (s0 + 1) * 16), hsrc + (c + 2) * JCHUNK + (s0 + 1) * 8);
            if (t < JCHUNK / 2)
                CP_ASYNC8(smem_u32(&jsm[b2][t]), jsrc + (c + 2) * (JCHUNK / 2) + t);
        }
        CP_COMMIT();

        // prefetch next chunk-pair's mask group during odd chunks
        if ((c & 1) && (c + 1 < NCHUNK)) {
            awn0 = adjp0[(c + 1) >> 1];
            awn1 = adjp1[(c + 1) >> 1];
        }

        const uint32_t hb = htb + b * HT_B;
        const uint2* jrow = jsm[b];

        // word pair selection (interleaved ballot layout): k = (2*tid)&3 in {0,2}
        const unsigned wlo0 = (tid & 1) ? awc0.z : awc0.x;
        const unsigned whi0 = (tid & 1) ? awc0.w : awc0.y;
        const unsigned wlo1 = (tid & 1) ? awc1.z : awc1.x;
        const unsigned whi1 = (tid & 1) ? awc1.w : awc1.y;
        const int pbase = (c & 1) * 16 + (tid >> 1);

        #pragma unroll
        for (int ks = 0; ks < 4; ++ks) {
            // B fragments: 4 n-tiles of 16 f-cols
            uint32_t bf[4][4];
            {
                const int grp  = lane >> 3;
                const int bkcB = (ks * 2 + (grp & 1)) * 16;
                const int rofs = (grp >> 1) * 8 + (lane & 7);
                #pragma unroll
                for (int np = 0; np < 4; ++np)
                    ldsm4(bf[np], hb + swz(np * 16 + rofs, bkcB));
            }
            // j factors: pair A = cols {ks*16+2tid, +1}, pair B = +8
            const uint2 jA = jrow[ks * 8 + tid];
            const uint2 jB = jrow[ks * 8 + tid + 4];
            // adj bits: bit position p = (c&1)*16 + ks*4 + (tid>>1); lo word -> even
            // col of the pair, hi word -> odd col; +2 for the B (+8) pair
            const int p = pbase + ks * 4;
            const unsigned sl0 = wlo0 >> p, sh0 = whi0 >> p;
            const unsigned sl1 = wlo1 >> p, sh1 = whi1 >> p;
            const unsigned b2A0 = (sl0 & 1u) | ((sh0 & 1u) << 1);
            const unsigned b2A1 = (sl1 & 1u) | ((sh1 & 1u) << 1);
            const unsigned b2B0 = ((sl0 >> 2) & 1u) | (((sh0 >> 2) & 1u) << 1);
            const unsigned b2B1 = ((sl1 >> 2) & 1u) | (((sh1 >> 2) & 1u) << 1);
            // generate A fragment: w = max(Ei*Ej, Ni*Nj) & adjmask  (half2, 2 cols/op)
            uint32_t af[4];
            af[0] = wgen(hE0, hN0, jA.x, jA.y, b2A0);
            af[1] = wgen(hE1, hN1, jA.x, jA.y, b2A1);
            af[2] = wgen(hE0, hN0, jB.x, jB.y, b2B0);
            af[3] = wgen(hE1, hN1, jB.x, jB.y, b2B1);
            // 8 HMMA + 1 Z-HMMA (ones column)
            #pragma unroll
            for (int np = 0; np < 4; ++np) {
                mma16816(acc[np * 2],     af, bf[np][0], bf[np][1]);
                mma16816(acc[np * 2 + 1], af, bf[np][2], bf[np][3]);
            }
            mma16816(accZ, af, oz0, oz1);
        }
        if (c & 1) { awc0 = awn0; awc1 = awn1; }
    }

    // ---- Z: col 0 of the Z-tile (held by tid==0 lanes) ----
    if (tid == 0) {
        float* zb = g_partZ + (size_t)(split * HEADS + head) * NN + i0;
        zb[rA]     = accZ[0];
        zb[rA + 8] = accZ[2];
    }

    // ---- epilogue: store unnormalized partial C ----
    {
        float* cbase = g_partC + (size_t)(split * HEADS + head) * NN * FOUT;
        float* p0 = cbase + (size_t)(i0 + rA) * FOUT + 2 * tid;
        float* p1 = cbase + (size_t)(i0 + rA + 8) * FOUT + 2 * tid;
        #pragma unroll
        for (int np = 0; np < 4; ++np) {
            #pragma unroll
            for (int p = 0; p < 2; ++p) {
                const int nt = np * 2 + p;
                const int cb = np * 16 + p * 8;
                *(float2*)(p0 + cb) = make_float2(acc[nt][0], acc[nt][1]);
                *(float2*)(p1 + cb) = make_float2(acc[nt][2], acc[nt][3]);
            }
        }
    }
}

// ---------------- kernel 3: combine splits, normalize, mean heads ----------
__global__ void __launch_bounds__(256) combine_kernel(float* __restrict__ out) {
    const int idx = blockIdx.x * 256 + threadIdx.x;   // i*64 + f
    const int i = idx >> 6;
    float r = 0.0f;
    #pragma unroll
    for (int h = 0; h < HEADS; ++h) {
        float cs = 0.0f, zs = 0.0f;
        #pragma unroll
        for (int s = 0; s < NSPLIT; ++s) {
            cs += g_partC[(size_t)(s * HEADS + h) * NN * FOUT + idx];
            zs += g_partZ[(size_t)(s * HEADS + h) * NN + i];
        }
        r += cs / zs;
    }
    out[idx] = 0.25f * r;
}

// ---------------- launcher ----------------
extern "C" void kernel_launch(void* const* d_in, const int* in_sizes, int n_in,
                              void* d_out, int out_size) {
    const float* x = nullptr;
    const int*   adj = nullptr;
    const float* W = nullptr;
    const float* a = nullptr;
    for (int i = 0; i < n_in; ++i) {
        switch (in_sizes[i]) {
            case 1048576:  x   = (const float*)d_in[i]; break;
            case 16777216: adj = (const int*)  d_in[i]; break;
            case 65536:    W   = (const float*)d_in[i]; break;
            case 128:      a   = (const float*)d_in[i]; break;
        }
    }
    float* out = (float*)d_out;

    gemm_h_kernel<<<NN / GROWS, 256>>>(x, W, a, adj);
    gat_mma_kernel<<<dim3(NN / ITILE, HEADS, NSPLIT), 256>>>();
    combine_kernel<<<NF / 256, 256>>>(out);
}